// round 17
// baseline (speedup 1.0000x reference)
#include <cuda_runtime.h>
#include <math.h>

#define BB 8
#define NN 2048
#define DD 1024
#define H1 128
#define FF 28
#define DK 64
#define NSTEPS 4
#define NSEG 8
#define NS5 4
#define BN (BB*NN)

// ---- scratch (static device globals; no runtime allocation) ----
static __device__ float  g_H[BN*H1];
static __device__ float  g_V[BN*DK];
static __device__ float  g_Q[BN*DK];
static __device__ float  g_K[BN*DK];
static __device__ float  g_compat[(size_t)BB*NN*NN];  // lower triangle valid
static __device__ float  g_ccur[BN];
static __device__ float4 g_cpack[BN];                 // (c1,c2,c3,c4)
static __device__ float  g_Zinv[BN];
static __device__ float  g_Rpart[NSEG][BN];           // partial col sums (recv)
static __device__ float  g_AV5[NS5][BN*DK];           // unnormalized AV partials
static __device__ float  g_Z5[NS5][BN];               // Z partials for k5
static __device__ float  g_AV[BN*DK];

// ============================================================
// fexp: FMA-pipe exp (no MUFU). k=rint(x*log2e), r=x-k*ln2
// (two-part), deg-6 Taylor (|r|<=0.347 -> rel err ~1.2e-7),
// exact 2^k via exponent-bit add (p in [0.70,1.42]).
// ============================================================
__device__ __forceinline__ float fexp(float x) {
    const float LOG2E  = 1.4426950408889634f;
    const float LN2_HI = 0.693145751953125f;    // exact high part
    const float LN2_LO = 1.42860677e-6f;
    int   ki = __float2int_rn(x * LOG2E);
    float kf = (float)ki;
    float r  = fmaf(-kf, LN2_HI, x);
    r = fmaf(-kf, LN2_LO, r);
    float p = 1.3888889e-3f;                     // 1/720
    p = fmaf(p, r, 8.3333333e-3f);               // 1/120
    p = fmaf(p, r, 4.1666667e-2f);               // 1/24
    p = fmaf(p, r, 1.6666667e-1f);               // 1/6
    p = fmaf(p, r, 5.0e-1f);
    p = fmaf(p, r, 1.0f);
    p = fmaf(p, r, 1.0f);
    return __int_as_float(__float_as_int(p) + (ki << 23));
}

// ============================================================
// K1: Y[16384,192] = X @ [W1|Wv]^T. 128x192 tile, 8x12 acc,
// double-buffered K-tile=16. 128 blocks.
// ============================================================
__global__ void __launch_bounds__(256) k1_gemm(const float* __restrict__ X,
        const float* __restrict__ w1, const float* __restrict__ b1,
        const float* __restrict__ wv) {
    __shared__ float Xs[2][16][132];
    __shared__ float Ws[2][16][200];
    const int t  = threadIdx.x;
    const int tx = t & 15, ty = t >> 4;
    const int r0 = blockIdx.x * 128;

    float acc[8][12];
    #pragma unroll
    for (int i = 0; i < 8; i++)
        #pragma unroll
        for (int j = 0; j < 12; j++) acc[i][j] = 0.f;

    #pragma unroll
    for (int i = 0; i < 8; i++) {
        int idx = t + i*256;  int r = idx >> 4, kk = idx & 15;
        Xs[0][kk][r] = X[(size_t)(r0+r)*DD + kk];
    }
    #pragma unroll
    for (int i = 0; i < 12; i++) {
        int idx = t + i*256;  int o = idx >> 4, kk = idx & 15;
        Ws[0][kk][o] = (o < H1) ? w1[o*DD + kk] : wv[(o-H1)*DD + kk];
    }
    __syncthreads();

    for (int kt = 0; kt < DD/16; kt++) {
        const int cur = kt & 1, nxt = cur ^ 1;
        float xr_st[8], wr_st[12];
        const bool more = (kt + 1 < DD/16);
        if (more) {
            int k0 = (kt+1)*16;
            #pragma unroll
            for (int i = 0; i < 8; i++) {
                int idx = t + i*256;  int r = idx >> 4, kk = idx & 15;
                xr_st[i] = X[(size_t)(r0+r)*DD + k0 + kk];
            }
            #pragma unroll
            for (int i = 0; i < 12; i++) {
                int idx = t + i*256;  int o = idx >> 4, kk = idx & 15;
                wr_st[i] = (o < H1) ? w1[o*DD + k0 + kk] : wv[(o-H1)*DD + k0 + kk];
            }
        }
        #pragma unroll
        for (int k = 0; k < 16; k++) {
            float4 xa = *reinterpret_cast<const float4*>(&Xs[cur][k][ty*4]);
            float4 xb = *reinterpret_cast<const float4*>(&Xs[cur][k][64 + ty*4]);
            float xr[8] = {xa.x,xa.y,xa.z,xa.w, xb.x,xb.y,xb.z,xb.w};
            float4 w0 = *reinterpret_cast<const float4*>(&Ws[cur][k][tx*4]);
            float4 w1v = *reinterpret_cast<const float4*>(&Ws[cur][k][64 + tx*4]);
            float4 w2v = *reinterpret_cast<const float4*>(&Ws[cur][k][128 + tx*4]);
            float wr[12] = {w0.x,w0.y,w0.z,w0.w, w1v.x,w1v.y,w1v.z,w1v.w,
                            w2v.x,w2v.y,w2v.z,w2v.w};
            #pragma unroll
            for (int i = 0; i < 8; i++)
                #pragma unroll
                for (int j = 0; j < 12; j++)
                    acc[i][j] = fmaf(xr[i], wr[j], acc[i][j]);
        }
        if (more) {
            #pragma unroll
            for (int i = 0; i < 8; i++) {
                int idx = t + i*256;  int r = idx >> 4, kk = idx & 15;
                Xs[nxt][kk][r] = xr_st[i];
            }
            #pragma unroll
            for (int i = 0; i < 12; i++) {
                int idx = t + i*256;  int o = idx >> 4, kk = idx & 15;
                Ws[nxt][kk][o] = wr_st[i];
            }
        }
        __syncthreads();
    }
    float4 b1a = *reinterpret_cast<const float4*>(&b1[tx*4]);
    float4 b1b = *reinterpret_cast<const float4*>(&b1[64 + tx*4]);
    float ba[8] = {b1a.x,b1a.y,b1a.z,b1a.w, b1b.x,b1b.y,b1b.z,b1b.w};
    #pragma unroll
    for (int i = 0; i < 8; i++) {
        int r = r0 + (i < 4 ? ty*4 + i : 64 + ty*4 + (i-4));
        float h[8];
        #pragma unroll
        for (int j = 0; j < 8; j++) {
            float v = acc[i][j] + ba[j];
            h[j] = 0.5f * v * (1.f + erff(v * 0.7071067811865476f));
        }
        *reinterpret_cast<float4*>(&g_H[(size_t)r*H1 + tx*4])      = make_float4(h[0],h[1],h[2],h[3]);
        *reinterpret_cast<float4*>(&g_H[(size_t)r*H1 + 64 + tx*4]) = make_float4(h[4],h[5],h[6],h[7]);
        *reinterpret_cast<float4*>(&g_V[(size_t)r*DK + tx*4]) =
            make_float4(acc[i][8], acc[i][9], acc[i][10], acc[i][11]);
    }
}

// ============================================================
// K2: features = sigmoid(H@W2^T+b2); Q/K; charge0; zero g_cpack
// ============================================================
__global__ void __launch_bounds__(256) k2_feat(const float* __restrict__ w2,
        const float* __restrict__ b2, const float* __restrict__ wq,
        const float* __restrict__ wk, const float* __restrict__ wc,
        const float* __restrict__ bc) {
    __shared__ float Hs[8][H1];
    __shared__ float Fs[8][FF];
    int warp = threadIdx.x >> 5, lane = threadIdx.x & 31;
    int row = blockIdx.x * 8 + warp;

    for (int k = lane; k < H1; k += 32) Hs[warp][k] = g_H[(size_t)row*H1 + k];
    __syncwarp();
    if (lane < FF) {
        float s = b2[lane];
        #pragma unroll 4
        for (int k = 0; k < H1; k++) s = fmaf(Hs[warp][k], w2[lane*H1 + k], s);
        Fs[warp][lane] = 1.f / (1.f + __expf(-s));
    }
    __syncwarp();
    #pragma unroll
    for (int half = 0; half < 2; half++) {
        int d = lane + half*32;
        float q = 0.f, kv = 0.f;
        #pragma unroll
        for (int j = 0; j < FF; j++) {
            float fv = Fs[warp][j];
            q  = fmaf(fv, wq[d*FF + j], q);
            kv = fmaf(fv, wk[d*FF + j], kv);
        }
        g_Q[(size_t)row*DK + d] = q;
        g_K[(size_t)row*DK + d] = kv;
    }
    if (lane == 0) {
        float s = bc[0];
        #pragma unroll
        for (int j = 0; j < FF; j++) s = fmaf(Fs[warp][j], wc[j], s);
        g_ccur[row] = 1.f / (1.f + __expf(-s));
        g_cpack[row] = make_float4(0.f, 0.f, 0.f, 0.f);
    }
}

// ============================================================
// K3: compat = Q@K^T/8.  128x128 tiles (triangle), 8x8 acc.
// ============================================================
__global__ void __launch_bounds__(256) k3_compat() {
    int tc = blockIdx.x, tr = blockIdx.y, b = blockIdx.z;
    if (tc > tr) return;
    __shared__ float Qs[32][132];
    __shared__ float Ks[32][132];
    int t = threadIdx.x, tx = t & 15, ty = t >> 4;
    int r0 = tr*128, c0 = tc*128;
    const float* Qb = g_Q + (size_t)b*NN*DK;
    const float* Kb = g_K + (size_t)b*NN*DK;

    float acc[8][8];
    #pragma unroll
    for (int i = 0; i < 8; i++)
        #pragma unroll
        for (int j = 0; j < 8; j++) acc[i][j] = 0.f;

    for (int kc = 0; kc < 2; kc++) {
        int kb0 = kc*32;
        #pragma unroll
        for (int i = 0; i < 16; i++) {
            int idx = t + i*256;
            int r = idx >> 5, kk = idx & 31;
            Qs[kk][r] = Qb[(size_t)(r0+r)*DK + kb0 + kk];
            Ks[kk][r] = Kb[(size_t)(c0+r)*DK + kb0 + kk];
        }
        __syncthreads();
        #pragma unroll
        for (int k = 0; k < 32; k++) {
            float4 qa = *reinterpret_cast<const float4*>(&Qs[k][ty*4]);
            float4 qb = *reinterpret_cast<const float4*>(&Qs[k][64 + ty*4]);
            float4 ka = *reinterpret_cast<const float4*>(&Ks[k][tx*4]);
            float4 kb = *reinterpret_cast<const float4*>(&Ks[k][64 + tx*4]);
            float xr[8] = {qa.x,qa.y,qa.z,qa.w, qb.x,qb.y,qb.z,qb.w};
            float wr[8] = {ka.x,ka.y,ka.z,ka.w, kb.x,kb.y,kb.z,kb.w};
            #pragma unroll
            for (int i = 0; i < 8; i++)
                #pragma unroll
                for (int j = 0; j < 8; j++)
                    acc[i][j] = fmaf(xr[i], wr[j], acc[i][j]);
        }
        __syncthreads();
    }
    float* Cb = g_compat + (size_t)b*NN*NN;
    #pragma unroll
    for (int i = 0; i < 8; i++) {
        int n = r0 + (i < 4 ? ty*4 + i : 64 + ty*4 + (i-4));
        *reinterpret_cast<float4*>(&Cb[(size_t)n*NN + c0 + tx*4]) =
            make_float4(acc[i][0]*0.125f, acc[i][1]*0.125f, acc[i][2]*0.125f, acc[i][3]*0.125f);
        *reinterpret_cast<float4*>(&Cb[(size_t)n*NN + c0 + 64 + tx*4]) =
            make_float4(acc[i][4]*0.125f, acc[i][5]*0.125f, acc[i][6]*0.125f, acc[i][7]*0.125f);
    }
}

// ============================================================
// kA_warp: Zinv via warp-per-row streaming, FMA-pipe exp.
// Each warp owns a complement row pair (p, 2047-p).
// No smem, no __syncthreads; shuffle reduction only.
// ============================================================
__global__ void __launch_bounds__(256) kA_warp(const float* __restrict__ step_p) {
    int w = threadIdx.x >> 5, lane = threadIdx.x & 31;
    int pair = blockIdx.x * 8 + w;          // 0..8191
    int b = pair >> 10;                      // pair / 1024
    int p = pair & 1023;
    float step = *step_p;
    const float* Cb = g_compat + (size_t)b*NN*NN;
    const float4* packb = g_cpack + b*NN;

    #pragma unroll
    for (int rr = 0; rr < 2; rr++) {
        int n = rr ? (NN - 1 - p) : p;
        float4 cn = packb[n];
        const float* crow = Cb + (size_t)n*NN;
        float z = 0.f;
        int m = lane;
        for (; m + 96 <= n; m += 128) {
            float  c0 = crow[m],    c1 = crow[m+32],  c2 = crow[m+64],  c3 = crow[m+96];
            float4 p0 = packb[m],   p1 = packb[m+32], p2 = packb[m+64], p3 = packb[m+96];
            float d0 = cn.x*p0.x + cn.y*p0.y + cn.z*p0.z + cn.w*p0.w;
            float d1 = cn.x*p1.x + cn.y*p1.y + cn.z*p1.z + cn.w*p1.w;
            float d2 = cn.x*p2.x + cn.y*p2.y + cn.z*p2.z + cn.w*p2.w;
            float d3 = cn.x*p3.x + cn.y*p3.y + cn.z*p3.z + cn.w*p3.w;
            float e0 = fexp(c0 * fmaf(step, d0, 1.f));
            float e1 = fexp(c1 * fmaf(step, d1, 1.f));
            float e2 = fexp(c2 * fmaf(step, d2, 1.f));
            float e3 = fexp(c3 * fmaf(step, d3, 1.f));
            z += (e0 + e1) + (e2 + e3);
        }
        for (; m <= n; m += 32) {
            float4 cm = packb[m];
            float dot = cn.x*cm.x + cn.y*cm.y + cn.z*cm.z + cn.w*cm.w;
            z += fexp(crow[m] * fmaf(step, dot, 1.f));
        }
        #pragma unroll
        for (int o = 16; o; o >>= 1) z += __shfl_xor_sync(0xffffffffu, z, o);
        if (lane == 0) g_Zinv[b*NN + n] = 1.f / z;
    }
}

// ============================================================
// kB_part: partial recv[m] = Σ exp(l)·Zinv[n] over this seg's
// n-tiles. Sync-free mainloop, FMA-pipe exp. 512 threads.
// ============================================================
__global__ void __launch_bounds__(512) kB_part(const float* __restrict__ step_p) {
    __shared__ float part[8][64];
    int b = blockIdx.z, seg = blockIdx.y;
    int tid = threadIdx.x, c = tid & 63, g = tid >> 6;
    float step = *step_p;
    const float* Cb = g_compat + (size_t)b*NN*NN;
    const float* Zb = g_Zinv + b*NN;
    const float4* packb = g_cpack + b*NN;

    #pragma unroll
    for (int phase = 0; phase < 2; phase++) {
        int tc = phase ? 31 - (int)blockIdx.x : (int)blockIdx.x;
        int m0 = tc*64;
        int m = m0 + c;
        float4 cm = packb[m];
        float acc = 0.f;

        for (int mt = tc + seg; mt < 32; mt += NSEG) {
            int n0 = mt*64;
            bool diag = (mt == tc);
            #pragma unroll
            for (int i = 0; i < 8; i++) {
                int r = g + i*8;
                if (!diag || r >= c) {
                    float4 cn = packb[n0 + r];           // warp-uniform
                    float zi = Zb[n0 + r];               // warp-uniform
                    float dot = cm.x*cn.x + cm.y*cn.y + cm.z*cn.z + cm.w*cn.w;
                    float e = fexp(Cb[(size_t)(n0+r)*NN + m] * fmaf(step, dot, 1.f));
                    acc = fmaf(e, zi, acc);
                }
            }
        }
        part[g][c] = acc;
        __syncthreads();
        if (tid < 64) {
            float s = 0.f;
            #pragma unroll
            for (int q = 0; q < 8; q++) s += part[q][c];
            g_Rpart[seg][b*NN + m0 + tid] = s;
        }
        __syncthreads();        // protect part before next phase
    }
}

// ============================================================
// kB2 (tiny): recv = Σ_seg Rpart; charge update; cpack comp t.
// ============================================================
__global__ void __launch_bounds__(256) kB2(int t, const float* __restrict__ decay_p) {
    int idx = blockIdx.x*256 + threadIdx.x;
    float r = 0.f;
    #pragma unroll
    for (int q = 0; q < NSEG; q++) r += g_Rpart[q][idx];
    float decay = *decay_p;
    float cprev = g_ccur[idx];
    float sig = 1.f / (1.f + __expf(-(r - 1.f)));
    float cnew = cprev * (1.f - decay*sig);
    g_ccur[idx] = cnew;
    float4 p = g_cpack[idx];
    if      (t == 0) p.x = cnew;
    else if (t == 1) p.y = cnew;
    else if (t == 2) p.z = cnew;
    else             p.w = cnew;
    g_cpack[idx] = p;
}

// ============================================================
// k5_part: segmented final attention, FMA-pipe exp.
// Block (p, seg, b): row-tiles p & 31-p, col-tiles mt ≡ seg (mod NS5).
// ============================================================
__global__ void __launch_bounds__(256) k5_part(const float* __restrict__ step_p) {
    __shared__ float Es[64][68];
    __shared__ float Vs[64][68];
    __shared__ float4 crp[64];
    int b = blockIdx.z, seg = blockIdx.y;
    int t = threadIdx.x, tx = t & 15, ty = t >> 4;
    float step = *step_p;
    const float* Cb = g_compat + (size_t)b*NN*NN;
    const float* Vb = g_V + (size_t)b*NN*DK;
    const int cload = t & 63;

    #pragma unroll
    for (int phase = 0; phase < 2; phase++) {
        int tr = phase ? 31 - (int)blockIdx.x : (int)blockIdx.x;
        int r0 = tr * 64;
        if (t < 64) crp[t] = g_cpack[b*NN + r0 + t];
        __syncthreads();

        float acc[4][4];
        #pragma unroll
        for (int i = 0; i < 4; i++)
            #pragma unroll
            for (int j = 0; j < 4; j++) acc[i][j] = 0.f;
        float zrun[4] = {0.f, 0.f, 0.f, 0.f};

        for (int mt = seg; mt <= tr; mt += NS5) {
            int m0 = mt * 64;
            bool diag = (mt == tr);
            float4 cc = g_cpack[b*NN + m0 + cload];
            #pragma unroll
            for (int i = 0; i < 16; i++) {
                int idx = t + i*256;
                int r = idx >> 6, c = idx & 63;
                float4 cr = crp[r];
                float dot = cr.x*cc.x + cr.y*cc.y + cr.z*cc.z + cr.w*cc.w;
                float e;
                if (diag && c > r) e = 0.f;
                else e = fexp(Cb[(size_t)(r0+r)*NN + m0 + c] * fmaf(step, dot, 1.f));
                Es[r][c] = e;
                Vs[r][c] = Vb[(size_t)(m0+r)*DK + c];
            }
            __syncthreads();
            #pragma unroll 4
            for (int k = 0; k < 64; k += 4) {
                float4 e0 = *reinterpret_cast<const float4*>(&Es[ty*4+0][k]);
                float4 e1 = *reinterpret_cast<const float4*>(&Es[ty*4+1][k]);
                float4 e2 = *reinterpret_cast<const float4*>(&Es[ty*4+2][k]);
                float4 e3 = *reinterpret_cast<const float4*>(&Es[ty*4+3][k]);
                float er[4][4] = {{e0.x,e0.y,e0.z,e0.w},{e1.x,e1.y,e1.z,e1.w},
                                  {e2.x,e2.y,e2.z,e2.w},{e3.x,e3.y,e3.z,e3.w}};
                #pragma unroll
                for (int i = 0; i < 4; i++)
                    zrun[i] += (er[i][0] + er[i][1]) + (er[i][2] + er[i][3]);
                #pragma unroll
                for (int q = 0; q < 4; q++) {
                    float4 v = *reinterpret_cast<const float4*>(&Vs[k+q][tx*4]);
                    float vr[4] = {v.x, v.y, v.z, v.w};
                    #pragma unroll
                    for (int i = 0; i < 4; i++)
                        #pragma unroll
                        for (int j = 0; j < 4; j++)
                            acc[i][j] = fmaf(er[i][q], vr[j], acc[i][j]);
                }
            }
            __syncthreads();
        }
        #pragma unroll
        for (int i = 0; i < 4; i++) {
            int row = b*NN + r0 + ty*4 + i;
            *reinterpret_cast<float4*>(&g_AV5[seg][(size_t)row*DK + tx*4]) =
                make_float4(acc[i][0], acc[i][1], acc[i][2], acc[i][3]);
            if (tx == 0) g_Z5[seg][row] = zrun[i];
        }
        __syncthreads();        // protect crp before next phase
    }
}

// ============================================================
// k5red: AV = (Σ_seg AV5) / (Σ_seg Z5). One float4 per thread.
// ============================================================
__global__ void __launch_bounds__(256) k5red() {
    int idx4 = blockIdx.x*256 + threadIdx.x;      // 0 .. BN*DK/4-1
    int row = idx4 >> 4;                           // DK/4 = 16 float4 per row
    float z = 0.f;
    #pragma unroll
    for (int q = 0; q < NS5; q++) z += g_Z5[q][row];
    float zi = 1.f / z;
    float4 a = make_float4(0.f, 0.f, 0.f, 0.f);
    #pragma unroll
    for (int q = 0; q < NS5; q++) {
        float4 p = *reinterpret_cast<const float4*>(&g_AV5[q][(size_t)idx4*4]);
        a.x += p.x; a.y += p.y; a.z += p.z; a.w += p.w;
    }
    *reinterpret_cast<float4*>(&g_AV[(size_t)idx4*4]) =
        make_float4(a.x*zi, a.y*zi, a.z*zi, a.w*zi);
}

// ============================================================
// K6: out = alpha * (AV @ wo^T). 128x128 tiles, 8x8 acc.
// ============================================================
__global__ void __launch_bounds__(256) k6_out(const float* __restrict__ wo,
        const float* __restrict__ mix_p, float* __restrict__ out) {
    __shared__ float As[32][132];
    __shared__ float Ws[32][132];
    int t = threadIdx.x, tx = t & 15, ty = t >> 4;
    int r0 = blockIdx.y * 128, c0 = blockIdx.x * 128;

    float acc[8][8];
    #pragma unroll
    for (int i = 0; i < 8; i++)
        #pragma unroll
        for (int j = 0; j < 8; j++) acc[i][j] = 0.f;

    for (int kc = 0; kc < 2; kc++) {
        int kb0 = kc*32;
        #pragma unroll
        for (int i = 0; i < 16; i++) {
            int idx = t + i*256;
            int r = idx >> 5, kk = idx & 31;
            As[kk][r] = g_AV[(size_t)(r0+r)*DK + kb0 + kk];
            Ws[kk][r] = wo[(size_t)(c0+r)*DK + kb0 + kk];
        }
        __syncthreads();
        #pragma unroll
        for (int k = 0; k < 32; k++) {
            float4 aa = *reinterpret_cast<const float4*>(&As[k][ty*4]);
            float4 ab = *reinterpret_cast<const float4*>(&As[k][64 + ty*4]);
            float4 wa = *reinterpret_cast<const float4*>(&Ws[k][tx*4]);
            float4 wb = *reinterpret_cast<const float4*>(&Ws[k][64 + tx*4]);
            float xr[8] = {aa.x,aa.y,aa.z,aa.w, ab.x,ab.y,ab.z,ab.w};
            float wr[8] = {wa.x,wa.y,wa.z,wa.w, wb.x,wb.y,wb.z,wb.w};
            #pragma unroll
            for (int i = 0; i < 8; i++)
                #pragma unroll
                for (int j = 0; j < 8; j++)
                    acc[i][j] = fmaf(xr[i], wr[j], acc[i][j]);
        }
        __syncthreads();
    }
    float alpha = 0.2f / (1.f + __expf(-mix_p[0]));
    #pragma unroll
    for (int i = 0; i < 8; i++) {
        int r = r0 + (i < 4 ? ty*4 + i : 64 + ty*4 + (i-4));
        *reinterpret_cast<float4*>(&out[(size_t)r*DD + c0 + tx*4]) =
            make_float4(acc[i][0]*alpha, acc[i][1]*alpha, acc[i][2]*alpha, acc[i][3]*alpha);
        *reinterpret_cast<float4*>(&out[(size_t)r*DD + c0 + 64 + tx*4]) =
            make_float4(acc[i][4]*alpha, acc[i][5]*alpha, acc[i][6]*alpha, acc[i][7]*alpha);
    }
}

// ============================================================
extern "C" void kernel_launch(void* const* d_in, const int* in_sizes, int n_in,
                              void* d_out, int out_size) {
    const float* X       = (const float*)d_in[0];
    const float* w1      = (const float*)d_in[2];
    const float* b1      = (const float*)d_in[3];
    const float* w2      = (const float*)d_in[4];
    const float* b2      = (const float*)d_in[5];
    const float* wq      = (const float*)d_in[6];
    const float* wk      = (const float*)d_in[7];
    const float* wc      = (const float*)d_in[8];
    const float* bc      = (const float*)d_in[9];
    const float* step_p  = (const float*)d_in[10];
    const float* decay_p = (const float*)d_in[11];
    const float* wv      = (const float*)d_in[12];
    const float* wo      = (const float*)d_in[13];
    const float* mix_p   = (const float*)d_in[14];
    float* out = (float*)d_out;

    k1_gemm<<<BN/128, 256>>>(X, w1, b1, wv);
    k2_feat<<<BN/8, 256>>>(w2, b2, wq, wk, wc, bc);
    k3_compat<<<dim3(NN/128, NN/128, BB), 256>>>();
    for (int t = 0; t < NSTEPS; t++) {
        kA_warp<<<BN/16, 256>>>(step_p);
        kB_part<<<dim3(16, NSEG, BB), 512>>>(step_p);
        kB2<<<BN/256, 256>>>(t, decay_p);
    }
    k5_part<<<dim3(16, NS5, BB), 256>>>(step_p);
    k5red<<<BN*DK/1024, 256>>>();
    k6_out<<<dim3(DD/128, BN/128), 256>>>(wo, mix_p, out);
}